// round 5
// baseline (speedup 1.0000x reference)
#include <cuda_runtime.h>
#include <cstdint>
#include <cstddef>

// Problem constants
#define NB     64      // batch N
#define LSEQ   512     // sequence length
#define DIN    1024    // input dim
#define HD     2048    // hidden dim
#define NGATE  4

// Kernel config
#define NCTA   128     // persistent CTAs (<= 148 SMs -> co-resident)
#define TPB    256
#define KPC    16      // hidden columns owned per CTA (128*16 = 2048)
#define KC     64      // K-chunk staged in SMEM
#define NCHUNK (HD / KC)   // 32
#define TSTR   72      // SMEM row stride (floats): 72 mod 32 = 8 -> conflict-free frag loads

// SMEM layout (floats): A0,A1,B0,B1 each 64*TSTR; then c[16*68]; s[64]; invw[64]; btot[64]
#define TILE_F   (64 * TSTR)
#define SMEM_FLOATS (4 * TILE_F + 16 * 68 + 64 + 64 + 64)
#define SMEM_BYTES  (SMEM_FLOATS * 4)

// ---------------- device scratch (no runtime allocation allowed) ----------------
__device__ float    g_Wt[(size_t)NCTA * NCHUNK * 64 * 64]; // tf32 weights, tiled+permuted (67MB)
__device__ float    g_h[2][NB * HD];     // double-buffered hidden state (tf32-rounded, k-permuted)
__device__ float    g_s[LSEQ * NB];      // invariant statistic sum(x_t)
__device__ volatile unsigned g_flag[NCTA];  // barrier arrival epochs
__device__ volatile unsigned g_go;          // barrier release epoch (persists across replays)

// ---------------- helpers ----------------
__device__ __forceinline__ unsigned f2tf32(float v) {
    unsigned u;
    asm("cvt.rna.tf32.f32 %0, %1;" : "=r"(u) : "f"(v));
    return u;
}

__device__ __forceinline__ void mma_tf32(float* d,
                                         unsigned a0, unsigned a1, unsigned a2, unsigned a3,
                                         unsigned b0, unsigned b1) {
    asm volatile(
        "mma.sync.aligned.m16n8k8.row.col.f32.tf32.tf32.f32 "
        "{%0,%1,%2,%3}, {%4,%5,%6,%7}, {%8,%9}, {%0,%1,%2,%3};"
        : "+f"(d[0]), "+f"(d[1]), "+f"(d[2]), "+f"(d[3])
        : "r"(a0), "r"(a1), "r"(a2), "r"(a3), "r"(b0), "r"(b1));
}

__device__ __forceinline__ void cp16(float* dst_smem, const float* src_gmem) {
    unsigned d = (unsigned)__cvta_generic_to_shared(dst_smem);
    asm volatile("cp.async.cg.shared.global [%0], [%1], 16;" :: "r"(d), "l"(src_gmem));
}
__device__ __forceinline__ void cp_commit() {
    asm volatile("cp.async.commit_group;");
}
template <int N>
__device__ __forceinline__ void cp_wait() {
    asm volatile("cp.async.wait_group %0;" :: "n"(N));
}

// k-permutation within 8-wide groups: logical col c -> stored slot ks so that
// logical (t, t+4) land at stored (2t, 2t+1)  [tf32 m16n8k8 fragment pairing].
// ks bits: ks0=c2, ks1=c0, ks2=c1   (high bits >=3 unchanged)
__device__ __forceinline__ int kperm(int c) {
    return (c & ~7) | ((c & 3) << 1) | ((c >> 2) & 1);
}
// inverse: c0=ks1, c1=ks2, c2=ks0
__device__ __forceinline__ int kperm_inv(int ks) {
    return (ks & ~7) | ((ks >> 1) & 3) | ((ks & 1) << 2);
}

// ---------------- pre-pass 1: s[t][n] = sum_d X[n][t][d] ----------------
__global__ void k_sum(const float* __restrict__ X) {
    int pair = blockIdx.x * (TPB / 32) + (threadIdx.x >> 5);
    if (pair >= LSEQ * NB) return;
    int t = pair / NB, n = pair % NB;
    const float* p = X + ((size_t)n * LSEQ + t) * DIN;
    int lane = threadIdx.x & 31;
    float v = 0.f;
    #pragma unroll 8
    for (int d = lane; d < DIN; d += 32) v += p[d];
    #pragma unroll
    for (int o = 16; o; o >>= 1) v += __shfl_xor_sync(0xFFFFFFFFu, v, o);
    if (lane == 0) g_s[t * NB + n] = v;
}

// ---------------- pre-pass 2: weights -> tf32, tiled per (cta, chunk), k-permuted ----------------
// dst linear o: ks = o&63; r = (o>>6)&63; ch = (o>>12)&31; cta = o>>17
// r = gate*16 + kl. src = lin_W[(gate*HD + cta*16 + kl)*HD + ch*64 + kperm_inv(ks)]
__global__ void k_wprep(const float* __restrict__ lin_W) {
    size_t o = (size_t)blockIdx.x * TPB + threadIdx.x;
    int ks  = (int)(o & 63);
    int r   = (int)((o >> 6) & 63);
    int ch  = (int)((o >> 12) & 31);
    int cta = (int)(o >> 17);
    int g = r >> 4, kl = r & 15;
    int c = kperm_inv(ks);
    float v = lin_W[((size_t)(g * HD + cta * KPC + kl)) * HD + ch * KC + c];
    g_Wt[o] = __uint_as_float(f2tf32(v));
}

// ---------------- persistent fused LSTM kernel ----------------
__global__ void __launch_bounds__(TPB, 1)
k_lstm(const float* __restrict__ H0,
       const float* __restrict__ inv_w,
       const float* __restrict__ inv_b,
       const float* __restrict__ lin_b,
       float* __restrict__ out) {
    extern __shared__ float sm[];
    float* Ab0 = sm;
    float* Ab1 = sm + TILE_F;
    float* Bb0 = sm + 2 * TILE_F;
    float* Bb1 = sm + 3 * TILE_F;
    float* csm = sm + 4 * TILE_F;      // [16][68]
    float* ssm = csm + 16 * 68;        // [64]
    float* invw_s = ssm + 64;          // [4][16]
    float* btot_s = invw_s + 64;       // [4][16]
    float* zsm = Ab0;                  // epilogue reuse: z[row][n], stride TSTR

    const int tid  = threadIdx.x;
    const int cta  = blockIdx.x;
    const int k0   = cta * KPC;
    const int wid  = tid >> 5;
    const int lane = tid & 31;
    const int gid  = lane >> 2;   // mma groupID
    const int tig  = lane & 3;    // mma threadID-in-group
    const int wm   = wid & 3;     // warp M-block (== gate)
    const int wn   = wid >> 2;    // warp N-half

    // barrier epoch base: release word persists across graph replays; monotonic
    __shared__ unsigned sh_base;
    if (tid == 0) sh_base = g_go;
    __syncthreads();
    const unsigned ebase = sh_base;

    // per-CTA constants
    if (tid < NGATE * KPC) {
        int g = tid >> 4, kk = tid & 15;
        invw_s[tid] = inv_w[g * HD + k0 + kk];
        btot_s[tid] = inv_b[g * HD + k0 + kk] + lin_b[g * HD + k0 + kk];
    }
    // init c = 0, h buf0 = tf32(H0), k-permuted slice
    #pragma unroll
    for (int q = 0; q < 4; q++) {
        int e = q * TPB + tid;
        int kk = e >> 6, n = e & 63;
        csm[kk * 68 + n] = 0.f;
        g_h[0][n * HD + k0 + kperm(kk)] = __uint_as_float(f2tf32(H0[n * HD + k0 + kk]));
    }

    // ---- grid barrier (epoch e): arrive + release ----
    auto gbar = [&](unsigned e) {
        __syncthreads();
        if (cta == 0) {
            if (tid > 0 && tid < NCTA) {
                while ((int)(g_flag[tid] - e) < 0) __nanosleep(32);
                __threadfence();
            }
            __syncthreads();
            if (tid == 0) { __threadfence(); g_go = e; }
        } else {
            if (tid == 0) {
                __threadfence();
                g_flag[cta] = e;
                while ((int)(g_go - e) < 0) __nanosleep(32);
                __threadfence();
            }
        }
        __syncthreads();
    };

    gbar(ebase + 1);

    float acc[4][4];

    for (int t = 0; t < LSEQ; t++) {
        const int rb = t & 1;
        const float* __restrict__ hprev = g_h[rb];
        float* __restrict__ hnew = g_h[rb ^ 1];
        const float* __restrict__ wbase = g_Wt + ((size_t)cta * NCHUNK << 12);

        #pragma unroll
        for (int j = 0; j < 4; j++)
            #pragma unroll
            for (int q = 0; q < 4; q++) acc[j][q] = 0.f;

        if (tid < 64) ssm[tid] = g_s[t * NB + tid];

        // ---- stage chunk (cp.async): A from tiled weights, B from hprev ----
        auto stage = [&](float* Ab, float* Bb, int ch) {
            const float* wsrc = wbase + ((size_t)ch << 12);
            const int hc = ch * KC;
            #pragma unroll
            for (int i = 0; i < 4; i++) {
                int idx = i * TPB + tid;          // 0..1023
                int r = idx >> 4, seg = (idx & 15) << 2;  // row, float offset
                cp16(Ab + r * TSTR + seg, wsrc + idx * 4);
                cp16(Bb + r * TSTR + seg, hprev + r * HD + hc + seg);
            }
            cp_commit();
        };

        stage(Ab0, Bb0, 0);
        #pragma unroll 1
        for (int ch = 0; ch < NCHUNK; ch++) {
            float* Ab = (ch & 1) ? Ab1 : Ab0;
            float* Bb = (ch & 1) ? Bb1 : Bb0;
            if (ch + 1 < NCHUNK) {
                stage((ch & 1) ? Ab0 : Ab1, (ch & 1) ? Bb0 : Bb1, ch + 1);
                cp_wait<1>();
            } else {
                cp_wait<0>();
            }
            __syncthreads();
            // compute: 8 mma K-steps of 8
            const float* Arow0 = Ab + (wm * 16 + gid) * TSTR;
            const float* Arow8 = Arow0 + 8 * TSTR;
            #pragma unroll
            for (int k8 = 0; k8 < 8; k8++) {
                const int kb = k8 * 8 + tig * 2;
                float2 a02 = *(const float2*)(Arow0 + kb);
                float2 a13 = *(const float2*)(Arow8 + kb);
                #pragma unroll
                for (int j = 0; j < 4; j++) {
                    float2 b01 = *(const float2*)(Bb + (wn * 32 + j * 8 + gid) * TSTR + kb);
                    mma_tf32(acc[j],
                             __float_as_uint(a02.x), __float_as_uint(a13.x),
                             __float_as_uint(a02.y), __float_as_uint(a13.y),
                             __float_as_uint(b01.x), __float_as_uint(b01.y));
                }
            }
            __syncthreads();   // protect buf for next iteration's stage
        }

        // ---- dump accumulators into zsm[row][n] ----
        #pragma unroll
        for (int j = 0; j < 4; j++) {
            int nc = wn * 32 + j * 8 + tig * 2;
            float* z0 = zsm + (wm * 16 + gid) * TSTR + nc;
            z0[0] = acc[j][0];
            z0[1] = acc[j][1];
            z0[8 * TSTR + 0] = acc[j][2];
            z0[8 * TSTR + 1] = acc[j][3];
        }
        __syncthreads();

        // ---- pointwise LSTM cell: 16 k x 64 n ----
        #pragma unroll
        for (int q = 0; q < 4; q++) {
            int e = q * TPB + tid;
            int kk = e >> 6, n = e & 63;
            float sv = ssm[n];
            float zi = zsm[(0 * 16 + kk) * TSTR + n] + sv * invw_s[0 * 16 + kk] + btot_s[0 * 16 + kk];
            float zf = zsm[(1 * 16 + kk) * TSTR + n] + sv * invw_s[1 * 16 + kk] + btot_s[1 * 16 + kk];
            float zg = zsm[(2 * 16 + kk) * TSTR + n] + sv * invw_s[2 * 16 + kk] + btot_s[2 * 16 + kk];
            float zo = zsm[(3 * 16 + kk) * TSTR + n] + sv * invw_s[3 * 16 + kk] + btot_s[3 * 16 + kk];
            float ig = 1.f / (1.f + __expf(-zi));
            float fg = 1.f / (1.f + __expf(-zf));
            float gg = tanhf(zg);
            float og = 1.f / (1.f + __expf(-zo));
            float c = fg * csm[kk * 68 + n] + ig * gg;
            csm[kk * 68 + n] = c;
            float h = og * tanhf(c);
            hnew[n * HD + k0 + kperm(kk)] = __uint_as_float(f2tf32(h));
            if (t == LSEQ - 1) out[(size_t)(k0 + kk) * NB + n] = h;
        }
        gbar(ebase + 2 + t);
    }
}

// ---------------- launch ----------------
extern "C" void kernel_launch(void* const* d_in, const int* in_sizes, int n_in,
                              void* d_out, int out_size) {
    const float* X     = (const float*)d_in[0];
    const float* H0    = (const float*)d_in[1];
    const float* inv_w = (const float*)d_in[2];
    const float* inv_b = (const float*)d_in[3];
    const float* lin_W = (const float*)d_in[4];
    const float* lin_b = (const float*)d_in[5];
    float* out = (float*)d_out;

    // Unconditional (no static guards): idempotent, deterministic, capture-safe.
    cudaFuncSetAttribute(k_lstm, cudaFuncAttributeMaxDynamicSharedMemorySize, SMEM_BYTES);

    // pre-pass: invariant statistic, one warp per (t, n)
    int pairs = LSEQ * NB;
    int blocks = (pairs + (TPB / 32) - 1) / (TPB / 32);
    k_sum<<<blocks, TPB>>>(X);

    // pre-pass: weight tiling/convert (tf32, k-permuted, per-CTA contiguous chunks)
    size_t wtot = (size_t)NCTA * NCHUNK * 64 * 64;
    k_wprep<<<(unsigned)(wtot / TPB), TPB>>>(lin_W);

    // persistent fused recurrence
    k_lstm<<<NCTA, TPB, SMEM_BYTES>>>(H0, inv_w, inv_b, lin_b, out);
}

// round 8
// speedup vs baseline: 1.5937x; 1.5937x over previous
#include <cuda_runtime.h>
#include <cuda_bf16.h>
#include <cstdint>
#include <cstddef>

// Problem constants
#define NB     64
#define LSEQ   512
#define DIN    1024
#define HD     2048
#define NGATE  4

// Kernel config
#define NCTA   128
#define TPB    256
#define KPC    16      // hidden columns owned per CTA
#define KC     64      // K-chunk staged in SMEM
#define NCHUNK (HD / KC)   // 32
#define BSTR   80      // tile row stride in bf16 units (160B): 40 floats == 8 mod 32 -> conflict-free

// SMEM byte layout
#define TILE_B   (64 * BSTR * 2)          // 10240 B per tile
#define OFF_A0   0
#define OFF_A1   (TILE_B)
#define OFF_B0   (2 * TILE_B)
#define OFF_B1   (3 * TILE_B)
#define OFF_Z    (4 * TILE_B)             // 64x68 fp32 = 17408
#define OFF_C    (OFF_Z + 64 * 68 * 4)    // 16x68 fp32 = 4352
#define OFF_S    (OFF_C + 16 * 68 * 4)    // 64 fp32
#define OFF_IW   (OFF_S + 256)            // 64 fp32
#define OFF_BT   (OFF_IW + 256)           // 64 fp32
#define SMEM_BYTES (OFF_BT + 256)

// ---------------- device scratch ----------------
__device__ __nv_bfloat16 g_Wt[(size_t)NCTA * NCHUNK * 64 * 64]; // bf16 weights, tiled+permuted (33.5MB)
__device__ __nv_bfloat16 g_h[2][NB * HD];   // hidden state (bf16, slot16-permuted)
__device__ float         g_s[LSEQ * NB];
__device__ volatile unsigned g_flag[NCTA];
__device__ volatile unsigned g_go;

// ---------------- helpers ----------------
// within-16 k permutation for m16n8k16 fragments: quads (2t,2t+1,2t+8,2t+9) adjacent
__device__ __forceinline__ int slot16(int k) {          // logical k (0..15) -> stored slot
    return (((k & 7) >> 1) << 2) | (((k >> 3) & 1) << 1) | (k & 1);
}
__device__ __forceinline__ int inv16(int s) {           // stored slot -> logical k
    return (((s >> 2) & 3) << 1) | (((s >> 1) & 1) << 3) | (s & 1);
}

__device__ __forceinline__ void mma_bf16(float* d,
                                         unsigned a0, unsigned a1, unsigned a2, unsigned a3,
                                         unsigned b0, unsigned b1) {
    asm volatile(
        "mma.sync.aligned.m16n8k16.row.col.f32.bf16.bf16.f32 "
        "{%0,%1,%2,%3}, {%4,%5,%6,%7}, {%8,%9}, {%0,%1,%2,%3};"
        : "+f"(d[0]), "+f"(d[1]), "+f"(d[2]), "+f"(d[3])
        : "r"(a0), "r"(a1), "r"(a2), "r"(a3), "r"(b0), "r"(b1));
}

__device__ __forceinline__ void cp16(void* dst_smem, const void* src_gmem) {
    unsigned d = (unsigned)__cvta_generic_to_shared(dst_smem);
    asm volatile("cp.async.cg.shared.global [%0], [%1], 16;" :: "r"(d), "l"(src_gmem));
}
__device__ __forceinline__ void cp_commit() { asm volatile("cp.async.commit_group;"); }
template <int N>
__device__ __forceinline__ void cp_wait() { asm volatile("cp.async.wait_group %0;" :: "n"(N)); }

// ---------------- pre-pass 1: s[t][n] = sum_d X[n][t][d] ----------------
__global__ void k_sum(const float* __restrict__ X) {
    int pair = blockIdx.x * (TPB / 32) + (threadIdx.x >> 5);
    if (pair >= LSEQ * NB) return;
    int t = pair / NB, n = pair % NB;
    const float* p = X + ((size_t)n * LSEQ + t) * DIN;
    int lane = threadIdx.x & 31;
    float v = 0.f;
    #pragma unroll 8
    for (int d = lane; d < DIN; d += 32) v += p[d];
    #pragma unroll
    for (int o = 16; o; o >>= 1) v += __shfl_xor_sync(0xFFFFFFFFu, v, o);
    if (lane == 0) g_s[t * NB + n] = v;
}

// ---------------- pre-pass 2: weights -> bf16, tiled per (cta,chunk), slot16-permuted ----------------
// dst o: ks=o&63 (stored col), r=(o>>6)&63 (row=gate*16+kl), ch=(o>>12)&31, cta=o>>17
__global__ void k_wprep(const float* __restrict__ lin_W) {
    size_t o = (size_t)blockIdx.x * TPB + threadIdx.x;
    int ks  = (int)(o & 63);
    int r   = (int)((o >> 6) & 63);
    int ch  = (int)((o >> 12) & 31);
    int cta = (int)(o >> 17);
    int g = r >> 4, kl = r & 15;
    int c = (ks & ~15) | inv16(ks & 15);   // logical k within chunk
    float v = lin_W[((size_t)(g * HD + cta * KPC + kl)) * HD + ch * KC + c];
    g_Wt[o] = __float2bfloat16(v);
}

// ---------------- persistent fused LSTM kernel ----------------
__global__ void __launch_bounds__(TPB, 1)
k_lstm(const float* __restrict__ H0,
       const float* __restrict__ inv_w,
       const float* __restrict__ inv_b,
       const float* __restrict__ lin_b,
       float* __restrict__ out) {
    extern __shared__ char smb[];
    __nv_bfloat16* Ab0 = (__nv_bfloat16*)(smb + OFF_A0);
    __nv_bfloat16* Ab1 = (__nv_bfloat16*)(smb + OFF_A1);
    __nv_bfloat16* Bb0 = (__nv_bfloat16*)(smb + OFF_B0);
    __nv_bfloat16* Bb1 = (__nv_bfloat16*)(smb + OFF_B1);
    float* zsm    = (float*)(smb + OFF_Z);    // [64][68]
    float* csm    = (float*)(smb + OFF_C);    // [16][68]
    float* ssm    = (float*)(smb + OFF_S);
    float* invw_s = (float*)(smb + OFF_IW);
    float* btot_s = (float*)(smb + OFF_BT);

    const int tid  = threadIdx.x;
    const int cta  = blockIdx.x;
    const int k0   = cta * KPC;
    const int wid  = tid >> 5;
    const int lane = tid & 31;
    const int gid  = lane >> 2;
    const int tig  = lane & 3;
    const int wm   = wid & 3;     // warp M-block (== gate)
    const int wn   = wid >> 2;    // warp N-half

    __shared__ unsigned sh_base;
    if (tid == 0) sh_base = g_go;
    __syncthreads();
    const unsigned ebase = sh_base;

    if (tid < NGATE * KPC) {
        int g = tid >> 4, kk = tid & 15;
        invw_s[tid] = inv_w[g * HD + k0 + kk];
        btot_s[tid] = inv_b[g * HD + k0 + kk] + lin_b[g * HD + k0 + kk];
    }
    #pragma unroll
    for (int q = 0; q < 4; q++) {
        int e = q * TPB + tid;
        int kk = e >> 6, n = e & 63;
        csm[kk * 68 + n] = 0.f;
        g_h[0][n * HD + k0 + slot16(kk)] = __float2bfloat16(H0[n * HD + k0 + kk]);
    }

    auto gbar = [&](unsigned e) {
        __syncthreads();
        if (cta == 0) {
            if (tid > 0 && tid < NCTA) {
                while ((int)(g_flag[tid] - e) < 0) __nanosleep(32);
                __threadfence();
            }
            __syncthreads();
            if (tid == 0) { __threadfence(); g_go = e; }
        } else {
            if (tid == 0) {
                __threadfence();
                g_flag[cta] = e;
                while ((int)(g_go - e) < 0) __nanosleep(32);
                __threadfence();
            }
        }
        __syncthreads();
    };

    gbar(ebase + 1);

    float acc[4][4];

    for (int t = 0; t < LSEQ; t++) {
        const int rb = t & 1;
        const __nv_bfloat16* __restrict__ hprev = g_h[rb];
        __nv_bfloat16* __restrict__ hnew = g_h[rb ^ 1];
        const __nv_bfloat16* __restrict__ wbase = g_Wt + (size_t)cta * NCHUNK * 4096;

        #pragma unroll
        for (int j = 0; j < 4; j++)
            #pragma unroll
            for (int q = 0; q < 4; q++) acc[j][q] = 0.f;

        if (tid < 64) ssm[tid] = g_s[t * NB + tid];

        // ---- stage one chunk: A (pre-tiled weights), B (hprev rows) ----
        auto stage = [&](__nv_bfloat16* Ab, __nv_bfloat16* Bb, int ch) {
            const __nv_bfloat16* wsrc = wbase + (size_t)ch * 4096;
            const int hc = ch * KC;
            #pragma unroll
            for (int i = 0; i < 2; i++) {
                int idx = i * TPB + tid;          // 0..511 (16B chunks)
                int r = idx >> 3, seg = idx & 7;  // row, 16B-seg (8 bf16)
                cp16(Ab + r * BSTR + seg * 8, wsrc + idx * 8);
                cp16(Bb + r * BSTR + seg * 8, hprev + r * HD + hc + seg * 8);
            }
            cp_commit();
        };

        stage(Ab0, Bb0, 0);
        #pragma unroll 1
        for (int ch = 0; ch < NCHUNK; ch++) {
            __nv_bfloat16* Ab = (ch & 1) ? Ab1 : Ab0;
            __nv_bfloat16* Bb = (ch & 1) ? Bb1 : Bb0;
            if (ch + 1 < NCHUNK) {
                stage((ch & 1) ? Ab0 : Ab1, (ch & 1) ? Bb0 : Bb1, ch + 1);
                cp_wait<1>();
            } else {
                cp_wait<0>();
            }
            __syncthreads();
            // 4 mma K16-steps per chunk
            const __nv_bfloat16* Ar0 = Ab + (wm * 16 + gid) * BSTR + tig * 4;
            const __nv_bfloat16* Ar8 = Ar0 + 8 * BSTR;
            const __nv_bfloat16* Bbase = Bb + (wn * 32 + gid) * BSTR + tig * 4;
            #pragma unroll
            for (int ks = 0; ks < 4; ks++) {
                uint2 a02 = *(const uint2*)(Ar0 + ks * 16);
                uint2 a13 = *(const uint2*)(Ar8 + ks * 16);
                #pragma unroll
                for (int j = 0; j < 4; j++) {
                    uint2 b01 = *(const uint2*)(Bbase + j * 8 * BSTR + ks * 16);
                    mma_bf16(acc[j], a02.x, a13.x, a02.y, a13.y, b01.x, b01.y);
                }
            }
            __syncthreads();   // protect buffer for next stage
        }

        // ---- dump accumulators into zsm[row][n] ----
        #pragma unroll
        for (int j = 0; j < 4; j++) {
            int nc = wn * 32 + j * 8 + tig * 2;
            float* z0 = zsm + (wm * 16 + gid) * 68 + nc;
            z0[0] = acc[j][0];
            z0[1] = acc[j][1];
            z0[8 * 68 + 0] = acc[j][2];
            z0[8 * 68 + 1] = acc[j][3];
        }
        __syncthreads();

        // ---- pointwise LSTM cell: 16 k x 64 n ----
        #pragma unroll
        for (int q = 0; q < 4; q++) {
            int e = q * TPB + tid;
            int kk = e >> 6, n = e & 63;
            float sv = ssm[n];
            float zi = zsm[(0 * 16 + kk) * 68 + n] + sv * invw_s[0 * 16 + kk] + btot_s[0 * 16 + kk];
            float zf = zsm[(1 * 16 + kk) * 68 + n] + sv * invw_s[1 * 16 + kk] + btot_s[1 * 16 + kk];
            float zg = zsm[(2 * 16 + kk) * 68 + n] + sv * invw_s[2 * 16 + kk] + btot_s[2 * 16 + kk];
            float zo = zsm[(3 * 16 + kk) * 68 + n] + sv * invw_s[3 * 16 + kk] + btot_s[3 * 16 + kk];
            float ig = 1.f / (1.f + __expf(-zi));
            float fg = 1.f / (1.f + __expf(-zf));
            float gg = tanhf(zg);
            float og = 1.f / (1.f + __expf(-zo));
            float c = fg * csm[kk * 68 + n] + ig * gg;
            csm[kk * 68 + n] = c;
            float h = og * tanhf(c);
            hnew[n * HD + k0 + slot16(kk)] = __float2bfloat16(h);
            if (t == LSEQ - 1) out[(size_t)(k0 + kk) * NB + n] = h;
        }
        gbar(ebase + 2 + t);
    }
}

// ---------------- launch ----------------
extern "C" void kernel_launch(void* const* d_in, const int* in_sizes, int n_in,
                              void* d_out, int out_size) {
    const float* X     = (const float*)d_in[0];
    const float* H0    = (const float*)d_in[1];
    const float* inv_w = (const float*)d_in[2];
    const float* inv_b = (const float*)d_in[3];
    const float* lin_W = (const float*)d_in[4];
    const float* lin_b = (const float*)d_in[5];
    float* out = (float*)d_out;

    cudaFuncSetAttribute(k_lstm, cudaFuncAttributeMaxDynamicSharedMemorySize, SMEM_BYTES);

    int pairs = LSEQ * NB;
    int blocks = (pairs + (TPB / 32) - 1) / (TPB / 32);
    k_sum<<<blocks, TPB>>>(X);

    size_t wtot = (size_t)NCTA * NCHUNK * 64 * 64;
    k_wprep<<<(unsigned)(wtot / TPB), TPB>>>(lin_W);

    k_lstm<<<NCTA, TPB, SMEM_BYTES>>>(H0, inv_w, inv_b, lin_b, out);
}